// round 1
// baseline (speedup 1.0000x reference)
#include <cuda_runtime.h>

// Problem constants (fixed by setup_inputs)
#define BB 512
#define HH 1024
#define OO 1024
#define AA 1024
#define SS 64
#define TT 128
#define ATTW 64

// Scratch (device globals: allocation-free). Zero-initialized at load; g_zero is never written.
__device__ __align__(256) float g_h[2][BB * HH];
__device__ __align__(256) float g_attnapp[BB * AA];
__device__ __align__(256) float g_gruin[BB * HH];
__device__ __align__(256) float g_rz[BB * 2 * HH];
__device__ __align__(256) float g_gin[BB * HH];
__device__ __align__(256) float g_ghn[BB * HH];
__device__ __align__(256) float g_zero[2048];

// ---------------------------------------------------------------------------
// Fused attention: logits = [dec|h] @ Wa^T + ba ; softmax(64) ; apply to enc.
// One block per batch row, 512 threads.
// ---------------------------------------------------------------------------
__global__ __launch_bounds__(512) void attn_fused_kernel(
    const float* __restrict__ dec, int ldd,
    const float* __restrict__ h,
    const float* __restrict__ enc,
    const float* __restrict__ Wa,
    const float* __restrict__ ba,
    float* __restrict__ attnapp)
{
    __shared__ __align__(16) float s_temp[2048];
    __shared__ float s_logit[ATTW];
    __shared__ float s_w[ATTW];

    const int b = blockIdx.x;
    const int tid = threadIdx.x;

    // load temp = [dec (1024) | h (1024)]
    s_temp[tid]        = dec[b * ldd + tid];
    s_temp[tid + 512]  = dec[b * ldd + tid + 512];
    s_temp[1024 + tid] = h[b * HH + tid];
    s_temp[1536 + tid] = h[b * HH + tid + 512];
    __syncthreads();

    const int warp = tid >> 5;
    const int lane = tid & 31;
    const float4* st4 = (const float4*)s_temp;

    // 16 warps x 4 outputs each = 64 logits, K = 2048
    #pragma unroll
    for (int j = 0; j < 4; ++j) {
        const int o = warp * 4 + j;
        const float4* wr4 = (const float4*)(Wa + o * 2048);
        float acc = 0.f;
        #pragma unroll
        for (int kk = 0; kk < 16; ++kk) {
            float4 wv = wr4[lane + 32 * kk];
            float4 tv = st4[lane + 32 * kk];
            acc += wv.x * tv.x + wv.y * tv.y + wv.z * tv.z + wv.w * tv.w;
        }
        #pragma unroll
        for (int off = 16; off > 0; off >>= 1)
            acc += __shfl_xor_sync(0xffffffffu, acc, off);
        if (lane == 0) s_logit[o] = acc + ba[o];
    }
    __syncthreads();

    // softmax over 64 (warp 0)
    if (warp == 0) {
        float v0 = s_logit[lane], v1 = s_logit[lane + 32];
        float m = fmaxf(v0, v1);
        #pragma unroll
        for (int off = 16; off > 0; off >>= 1)
            m = fmaxf(m, __shfl_xor_sync(0xffffffffu, m, off));
        float e0 = expf(v0 - m), e1 = expf(v1 - m);
        float s = e0 + e1;
        #pragma unroll
        for (int off = 16; off > 0; off >>= 1)
            s += __shfl_xor_sync(0xffffffffu, s, off);
        float inv = 1.f / s;
        s_w[lane] = e0 * inv;
        s_w[lane + 32] = e1 * inv;
    }
    __syncthreads();

    // apply: out[d] = sum_s w[s] * enc[b,s,d]
    #pragma unroll 1
    for (int d = tid; d < AA; d += 512) {
        const float* ep = enc + (size_t)b * SS * AA + d;
        float acc = 0.f;
        #pragma unroll
        for (int s = 0; s < SS; ++s) acc += s_w[s] * ep[s * AA];
        attnapp[b * AA + d] = acc;
    }
}

// ---------------------------------------------------------------------------
// Tiled fp32 GEMM: C[M,N] = act( A1[M,K1] W1[N,K1]^T + A2[M,K2] W2[N,K2]^T
//                                + bias1 + bias2 )
// BM=BN=64, BK=16, 256 threads, 4x4 micro-tile. All dims multiples of 64/16.
// lda may be 0 (broadcast a single zero row).
// ---------------------------------------------------------------------------
__global__ __launch_bounds__(256) void gemm_dual_kernel(
    const float* __restrict__ A1, int lda1, int K1,
    const float* __restrict__ W1, int ldw1,
    const float* __restrict__ A2, int lda2, int K2,
    const float* __restrict__ W2, int ldw2,
    const float* __restrict__ bias1, const float* __restrict__ bias2,
    float* __restrict__ C, int ldc, int relu)
{
    __shared__ __align__(16) float As[16][68];
    __shared__ __align__(16) float Ws[16][68];

    const int tid = threadIdx.x;
    const int bm = blockIdx.y * 64;
    const int bn = blockIdx.x * 64;
    const int ty = tid >> 4;         // 0..15 -> row group
    const int tx = tid & 15;         // 0..15 -> col group
    const int lr = tid >> 2;         // 0..63 loader row
    const int lc = (tid & 3) << 2;   // 0,4,8,12 loader k-offset

    float acc[4][4];
    #pragma unroll
    for (int i = 0; i < 4; ++i)
        #pragma unroll
        for (int j = 0; j < 4; ++j) acc[i][j] = 0.f;

    #pragma unroll 1
    for (int seg = 0; seg < 2; ++seg) {
        const float* A = seg ? A2 : A1;
        const float* W = seg ? W2 : W1;
        const int lda  = seg ? lda2 : lda1;
        const int ldw  = seg ? ldw2 : ldw1;
        const int K    = seg ? K2 : K1;
        const float* Ap = A + (bm + lr) * lda + lc;
        const float* Wp = W + (bn + lr) * ldw + lc;

        for (int k0 = 0; k0 < K; k0 += 16) {
            float4 av = *(const float4*)(Ap + k0);
            float4 wv = *(const float4*)(Wp + k0);
            As[lc + 0][lr] = av.x; As[lc + 1][lr] = av.y;
            As[lc + 2][lr] = av.z; As[lc + 3][lr] = av.w;
            Ws[lc + 0][lr] = wv.x; Ws[lc + 1][lr] = wv.y;
            Ws[lc + 2][lr] = wv.z; Ws[lc + 3][lr] = wv.w;
            __syncthreads();
            #pragma unroll
            for (int kk = 0; kk < 16; ++kk) {
                float4 a = *(const float4*)&As[kk][ty << 2];
                float4 w = *(const float4*)&Ws[kk][tx << 2];
                float af[4] = {a.x, a.y, a.z, a.w};
                float wf[4] = {w.x, w.y, w.z, w.w};
                #pragma unroll
                for (int i = 0; i < 4; ++i)
                    #pragma unroll
                    for (int j = 0; j < 4; ++j)
                        acc[i][j] += af[i] * wf[j];
            }
            __syncthreads();
        }
    }

    #pragma unroll
    for (int j = 0; j < 4; ++j) {
        const int n = bn + (tx << 2) + j;
        float bv = (bias1 ? bias1[n] : 0.f) + (bias2 ? bias2[n] : 0.f);
        #pragma unroll
        for (int i = 0; i < 4; ++i) {
            float v = acc[i][j] + bv;
            if (relu) v = fmaxf(v, 0.f);
            C[(bm + (ty << 2) + i) * ldc + n] = v;
        }
    }
}

// ---------------------------------------------------------------------------
// GRU gate fusion: r,z from rz-pre; n = tanh(gin + r*ghn); h' = (1-z)n + z h
// ---------------------------------------------------------------------------
__global__ __launch_bounds__(256) void gru_gate_kernel(
    const float* __restrict__ rz,
    const float* __restrict__ gin,
    const float* __restrict__ ghn,
    const float* __restrict__ h,
    float* __restrict__ hn)
{
    const int i = blockIdx.x * 256 + threadIdx.x;   // 0 .. B*H-1
    const int b = i >> 10;
    const int d = i & 1023;
    float pr = rz[(b << 11) + d];
    float pz = rz[(b << 11) + 1024 + d];
    float r = 1.f / (1.f + expf(-pr));
    float z = 1.f / (1.f + expf(-pz));
    float n = tanhf(gin[i] + r * ghn[i]);
    hn[i] = (1.f - z) * n + z * h[i];
}

__global__ void copy_kernel(const float* __restrict__ src,
                            float* __restrict__ dst, int n)
{
    int i = blockIdx.x * blockDim.x + threadIdx.x;
    if (i < n) dst[i] = src[i];
}

// ---------------------------------------------------------------------------
extern "C" void kernel_launch(void* const* d_in, const int* in_sizes, int n_in,
                              void* d_out, int out_size)
{
    const float* enc = (const float*)d_in[0];
    const float* hid = (const float*)d_in[1];   // [1,B,H] contiguous
    // d_in[2] = max_length scalar (fixed at 128 by setup_inputs)
    const float* Wa  = (const float*)d_in[3];
    const float* ba  = (const float*)d_in[4];
    const float* Wc  = (const float*)d_in[5];
    const float* bc  = (const float*)d_in[6];
    const float* Wih = (const float*)d_in[7];
    const float* Whh = (const float*)d_in[8];
    const float* bih = (const float*)d_in[9];
    const float* bhh = (const float*)d_in[10];
    const float* Wo  = (const float*)d_in[11];
    const float* bo  = (const float*)d_in[12];

    float* outseq = (float*)d_out;                       // [B, T, O]
    float* outh   = outseq + (size_t)BB * TT * OO;       // [1, B, H]

    float *ph, *pattn, *pgruin, *prz, *pgin, *pghn, *pzero;
    cudaGetSymbolAddress((void**)&ph,     g_h);
    cudaGetSymbolAddress((void**)&pattn,  g_attnapp);
    cudaGetSymbolAddress((void**)&pgruin, g_gruin);
    cudaGetSymbolAddress((void**)&prz,    g_rz);
    cudaGetSymbolAddress((void**)&pgin,   g_gin);
    cudaGetSymbolAddress((void**)&pghn,   g_ghn);
    cudaGetSymbolAddress((void**)&pzero,  g_zero);

    float* hbuf0 = ph;
    float* hbuf1 = ph + BB * HH;

    const dim3 gN1024(HH / 64, BB / 64);     // 16 x 8 = 128 blocks
    const dim3 gN2048(2 * HH / 64, BB / 64); // 32 x 8 = 256 blocks

    for (int t = 0; t < TT; ++t) {
        const float* hcur = (t == 0) ? hid : ((t & 1) ? hbuf1 : hbuf0);
        float* hnext = (t & 1) ? hbuf0 : hbuf1;
        const float* dec = (t == 0) ? pzero : (outseq + (t - 1) * OO);
        const int ldd = (t == 0) ? 0 : TT * OO;

        // attention: logits + softmax + apply
        attn_fused_kernel<<<BB, 512>>>(dec, ldd, hcur, enc, Wa, ba, pattn);

        // gru_in = relu([dec|attn] @ Wc^T + bc)
        gemm_dual_kernel<<<gN1024, 256>>>(
            dec, ldd, OO, Wc, OO + AA,
            pattn, AA, AA, Wc + OO, OO + AA,
            bc, nullptr, pgruin, HH, 1);

        // r,z pre-activations: gru_in @ Wih[0:2H]^T + h @ Whh[0:2H]^T + biases
        gemm_dual_kernel<<<gN2048, 256>>>(
            pgruin, HH, HH, Wih, HH,
            hcur, HH, HH, Whh, HH,
            bih, bhh, prz, 2 * HH, 0);

        // n gate inputs (separate, since n = tanh(gin + r*ghn))
        gemm_dual_kernel<<<gN1024, 256>>>(
            pgruin, HH, HH, Wih + 2 * HH * HH, HH,
            pzero, 0, 0, pzero, 0,
            bih + 2 * HH, nullptr, pgin, HH, 0);

        gemm_dual_kernel<<<gN1024, 256>>>(
            hcur, HH, HH, Whh + 2 * HH * HH, HH,
            pzero, 0, 0, pzero, 0,
            bhh + 2 * HH, nullptr, pghn, HH, 0);

        // gate fusion -> h_next
        gru_gate_kernel<<<BB * HH / 256, 256>>>(prz, pgin, pghn, hcur, hnext);

        // out_tok = h_next @ Wo^T + bo, written in place into output_seq[:, t, :]
        gemm_dual_kernel<<<gN1024, 256>>>(
            hnext, HH, HH, Wo, HH,
            pzero, 0, 0, pzero, 0,
            bo, nullptr, outseq + t * OO, TT * OO, 0);
    }

    // final hidden state (after step 127, lives in hbuf0)
    if (out_size >= BB * TT * OO + BB * HH) {
        copy_kernel<<<(BB * HH + 1023) / 1024, 1024>>>(hbuf0, outh, BB * HH);
    }
}

// round 2
// speedup vs baseline: 2.1607x; 2.1607x over previous
#include <cuda_runtime.h>
#include <cuda_bf16.h>
#include <cstdint>

// Problem constants (fixed by setup_inputs)
#define BB 512
#define HH 1024
#define OO 1024
#define AA 1024
#define SS 64
#define TT 128

// ---------------------------------------------------------------------------
// Device-global scratch (allocation-free)
// ---------------------------------------------------------------------------
// Split weights (bf16 hi/lo)
__device__ __align__(256) __nv_bfloat16 g_Wc_hi[1024 * 2048];
__device__ __align__(256) __nv_bfloat16 g_Wc_lo[1024 * 2048];
__device__ __align__(256) __nv_bfloat16 g_Wih_hi[3072 * 1024];
__device__ __align__(256) __nv_bfloat16 g_Wih_lo[3072 * 1024];
__device__ __align__(256) __nv_bfloat16 g_Whh_hi[3072 * 1024];
__device__ __align__(256) __nv_bfloat16 g_Whh_lo[3072 * 1024];
__device__ __align__(256) __nv_bfloat16 g_Wo_hi[1024 * 1024];
__device__ __align__(256) __nv_bfloat16 g_Wo_lo[1024 * 1024];
// Activations
__device__ __align__(256) __nv_bfloat16 g_actC_hi[512 * 2048]; // [dec | attn]
__device__ __align__(256) __nv_bfloat16 g_actC_lo[512 * 2048];
__device__ __align__(256) __nv_bfloat16 g_gruin_hi[512 * 1024];
__device__ __align__(256) __nv_bfloat16 g_gruin_lo[512 * 1024];
__device__ __align__(256) __nv_bfloat16 g_h_hi[512 * 1024];
__device__ __align__(256) __nv_bfloat16 g_h_lo[512 * 1024];
__device__ __align__(256) float g_h[512 * 1024];
__device__ __align__(256) float g_gi[512 * 3072];
__device__ __align__(256) float g_gh[512 * 3072];
__device__ __align__(256) float g_zero[2048];

// ---------------------------------------------------------------------------
// Helpers
// ---------------------------------------------------------------------------
__device__ __forceinline__ void split2(float v, __nv_bfloat16& hi, __nv_bfloat16& lo) {
    hi = __float2bfloat16(v);
    lo = __float2bfloat16(v - __bfloat162float(hi));
}

__device__ __forceinline__ void ldsm_x4(uint32_t* r, uint32_t addr) {
    asm volatile("ldmatrix.sync.aligned.m8n8.x4.shared.b16 {%0,%1,%2,%3}, [%4];\n"
                 : "=r"(r[0]), "=r"(r[1]), "=r"(r[2]), "=r"(r[3])
                 : "r"(addr));
}

__device__ __forceinline__ void mma_bf16(float* c, const uint32_t* a, const uint32_t* b) {
    asm volatile(
        "mma.sync.aligned.m16n8k16.row.col.f32.bf16.bf16.f32 "
        "{%0,%1,%2,%3}, {%4,%5,%6,%7}, {%8,%9}, {%0,%1,%2,%3};\n"
        : "+f"(c[0]), "+f"(c[1]), "+f"(c[2]), "+f"(c[3])
        : "r"(a[0]), "r"(a[1]), "r"(a[2]), "r"(a[3]), "r"(b[0]), "r"(b[1]));
}

__device__ __forceinline__ void cp16(void* dst_smem, const void* src) {
    uint32_t d = (uint32_t)__cvta_generic_to_shared(dst_smem);
    asm volatile("cp.async.cg.shared.global [%0], [%1], 16;\n" :: "r"(d), "l"(src));
}
#define CP_COMMIT() asm volatile("cp.async.commit_group;\n" ::: "memory")
#define CP_WAIT1()  asm volatile("cp.async.wait_group 1;\n" ::: "memory")

// ---------------------------------------------------------------------------
// bf16-split GEMM:  C[M,N] = A[M,K] @ W[N,K]^T + bias, computed as
// Ahi@Whi + Ahi@Wlo + Alo@Whi with fp32 accumulation (fp32-class accuracy).
// BM=BN=64, BK=32, 128 threads (4 warps as 2x2, warp tile 32x32).
// mode 0: fp32 out      mode 1: relu -> split bf16 out   mode 2: fp32 + split
// blockIdx.z==1 selects the second problem set (for batching gi & gh).
// ---------------------------------------------------------------------------
__global__ __launch_bounds__(128) void gemm_split_kernel(
    const __nv_bfloat16* __restrict__ Ahi, const __nv_bfloat16* __restrict__ Alo, int lda,
    const __nv_bfloat16* __restrict__ Whi, const __nv_bfloat16* __restrict__ Wlo,
    int K, const float* __restrict__ bias,
    float* __restrict__ Cf, int ldc,
    __nv_bfloat16* __restrict__ Chi, __nv_bfloat16* __restrict__ Clo, int ldch,
    int mode,
    const __nv_bfloat16* A2hi, const __nv_bfloat16* A2lo,
    const __nv_bfloat16* W2hi, const __nv_bfloat16* W2lo,
    const float* bias2, float* Cf2)
{
    if (blockIdx.z) {
        Ahi = A2hi; Alo = A2lo; Whi = W2hi; Wlo = W2lo; bias = bias2; Cf = Cf2;
    }

    __shared__ __nv_bfloat16 sA[2][64 * 40];
    __shared__ __nv_bfloat16 sW[2][64 * 40];

    const int tid = threadIdx.x;
    const int m0 = blockIdx.y * 64;
    const int n0 = blockIdx.x * 64;
    const int KIT = K >> 5;
    const int NIT = 3 * KIT;

    // loader: thread handles rows (tid>>2) and (tid>>2)+32, k-chunk (tid&3)*8
    const int arow = tid >> 2;
    const int acol = (tid & 3) << 3;

    const int warp = tid >> 5, lane = tid & 31;
    const int wm = (warp >> 1) << 5;   // 0 / 32
    const int wn = (warp & 1) << 5;    // 0 / 32

    // precompute ldmatrix smem addresses (element offsets; x2 bytes at use)
    const int a_row_l = wm + (lane & 15);
    const int a_col_l = (lane >> 4) << 3;
    const int g = lane >> 3;
    const int w_row_l = wn + ((g >> 1) << 3) + (lane & 7);
    const int w_col_l = (g & 1) << 3;

    float acc[2][4][4];
#pragma unroll
    for (int mi = 0; mi < 2; ++mi)
#pragma unroll
        for (int nf = 0; nf < 4; ++nf)
#pragma unroll
            for (int q = 0; q < 4; ++q) acc[mi][nf][q] = 0.f;

    auto load_stage = [&](int it) {
        int p = (it >= 2 * KIT) ? 2 : (it >= KIT ? 1 : 0);
        int k0 = (it - p * KIT) << 5;
        const __nv_bfloat16* As = (p < 2) ? Ahi : Alo;
        const __nv_bfloat16* Ws = (p == 1) ? Wlo : Whi;
        int buf = it & 1;
        const __nv_bfloat16* ag = As + (size_t)(m0 + arow) * lda + k0 + acol;
        cp16(&sA[buf][arow * 40 + acol], ag);
        cp16(&sA[buf][(arow + 32) * 40 + acol], ag + (size_t)32 * lda);
        const __nv_bfloat16* wg = Ws + (size_t)(n0 + arow) * K + k0 + acol;
        cp16(&sW[buf][arow * 40 + acol], wg);
        cp16(&sW[buf][(arow + 32) * 40 + acol], wg + (size_t)32 * K);
    };

    load_stage(0); CP_COMMIT();
    load_stage(1); CP_COMMIT();

    for (int it = 0; it < NIT; ++it) {
        CP_WAIT1();
        __syncthreads();
        const int buf = it & 1;
        uint32_t sA_base = (uint32_t)__cvta_generic_to_shared(&sA[buf][0]);
        uint32_t sW_base = (uint32_t)__cvta_generic_to_shared(&sW[buf][0]);

        uint32_t a[2][2][4];
        uint32_t b[2][4][2];
#pragma unroll
        for (int mi = 0; mi < 2; ++mi)
#pragma unroll
            for (int ki = 0; ki < 2; ++ki) {
                uint32_t addr = sA_base +
                    (uint32_t)(((a_row_l + mi * 16) * 40 + a_col_l + ki * 16) * 2);
                ldsm_x4(a[mi][ki], addr);
            }
#pragma unroll
        for (int nh = 0; nh < 2; ++nh)
#pragma unroll
            for (int ki = 0; ki < 2; ++ki) {
                uint32_t r[4];
                uint32_t addr = sW_base +
                    (uint32_t)(((w_row_l + nh * 16) * 40 + w_col_l + ki * 16) * 2);
                ldsm_x4(r, addr);
                b[ki][nh * 2 + 0][0] = r[0];
                b[ki][nh * 2 + 0][1] = r[1];
                b[ki][nh * 2 + 1][0] = r[2];
                b[ki][nh * 2 + 1][1] = r[3];
            }
#pragma unroll
        for (int ki = 0; ki < 2; ++ki)
#pragma unroll
            for (int mi = 0; mi < 2; ++mi)
#pragma unroll
                for (int nf = 0; nf < 4; ++nf)
                    mma_bf16(acc[mi][nf], a[mi][ki], b[ki][nf]);
        __syncthreads();
        if (it + 2 < NIT) load_stage(it + 2);
        CP_COMMIT();
    }

    // Epilogue
    const int rbase = m0 + wm + (lane >> 2);
    const int cbase = n0 + wn + ((lane & 3) << 1);
#pragma unroll
    for (int mi = 0; mi < 2; ++mi) {
#pragma unroll
        for (int nf = 0; nf < 4; ++nf) {
            const int c = cbase + (nf << 3);
            const float b0 = bias[c], b1 = bias[c + 1];
#pragma unroll
            for (int half = 0; half < 2; ++half) {
                const int r = rbase + (mi << 4) + (half << 3);
                float v0 = acc[mi][nf][half * 2 + 0] + b0;
                float v1 = acc[mi][nf][half * 2 + 1] + b1;
                if (mode == 0) {
                    float2 fv = make_float2(v0, v1);
                    *(float2*)&Cf[(size_t)r * ldc + c] = fv;
                } else if (mode == 1) {
                    v0 = fmaxf(v0, 0.f); v1 = fmaxf(v1, 0.f);
                    __nv_bfloat162 hv, lv;
                    split2(v0, hv.x, lv.x); split2(v1, hv.y, lv.y);
                    *(__nv_bfloat162*)&Chi[(size_t)r * ldch + c] = hv;
                    *(__nv_bfloat162*)&Clo[(size_t)r * ldch + c] = lv;
                } else {
                    float2 fv = make_float2(v0, v1);
                    *(float2*)&Cf[(size_t)r * ldc + c] = fv;
                    __nv_bfloat162 hv, lv;
                    split2(v0, hv.x, lv.x); split2(v1, hv.y, lv.y);
                    *(__nv_bfloat162*)&Chi[(size_t)r * ldch + c] = hv;
                    *(__nv_bfloat162*)&Clo[(size_t)r * ldch + c] = lv;
                }
            }
        }
    }
}

// ---------------------------------------------------------------------------
// Fused attention: logits (fp32) + softmax + apply; 4 batch rows / block.
// Writes attn_applied (split bf16) into actC columns [1024, 2048).
// ---------------------------------------------------------------------------
__global__ __launch_bounds__(512) void attn_kernel(
    const float* __restrict__ dec, int ldd,
    const float* __restrict__ h,
    const float* __restrict__ enc,
    const float* __restrict__ Wa, const float* __restrict__ ba,
    __nv_bfloat16* __restrict__ actChi, __nv_bfloat16* __restrict__ actClo)
{
    __shared__ float s_temp[4][2048];
    __shared__ float s_logit[4][64];
    __shared__ float s_w[4][64];

    const int tid = threadIdx.x;
    const int bg = blockIdx.x << 2;

    // load temp = [dec | h] for 4 batch rows
    for (int i = tid; i < 4 * 2048; i += 512) {
        const int bi = i >> 11, j = i & 2047;
        float v = (j < 1024) ? dec[(size_t)(bg + bi) * ldd + j]
                             : h[(size_t)(bg + bi) * 1024 + (j - 1024)];
        s_temp[bi][j] = v;
    }
    __syncthreads();

    const int warp = tid >> 5, lane = tid & 31;
    const int bi = warp & 3, og = warp >> 2;
    const float4* t4 = (const float4*)s_temp[bi];

#pragma unroll 1
    for (int j = 0; j < 16; ++j) {
        const int o = og * 16 + j;
        const float4* w4 = (const float4*)(Wa + (size_t)o * 2048);
        float acc = 0.f;
#pragma unroll
        for (int i = 0; i < 16; ++i) {
            float4 wv = w4[lane + (i << 5)];
            float4 tv = t4[lane + (i << 5)];
            acc = fmaf(wv.x, tv.x, fmaf(wv.y, tv.y,
                  fmaf(wv.z, tv.z, fmaf(wv.w, tv.w, acc))));
        }
#pragma unroll
        for (int off = 16; off > 0; off >>= 1)
            acc += __shfl_xor_sync(0xffffffffu, acc, off);
        if (lane == 0) s_logit[bi][o] = acc + ba[o];
    }
    __syncthreads();

    if (warp < 4) {
        float v0 = s_logit[warp][lane], v1 = s_logit[warp][lane + 32];
        float m = fmaxf(v0, v1);
#pragma unroll
        for (int off = 16; off > 0; off >>= 1)
            m = fmaxf(m, __shfl_xor_sync(0xffffffffu, m, off));
        float e0 = expf(v0 - m), e1 = expf(v1 - m);
        float s = e0 + e1;
#pragma unroll
        for (int off = 16; off > 0; off >>= 1)
            s += __shfl_xor_sync(0xffffffffu, s, off);
        float inv = 1.f / s;
        s_w[warp][lane] = e0 * inv;
        s_w[warp][lane + 32] = e1 * inv;
    }
    __syncthreads();

    // apply: attn[d] = sum_s w[s] * enc[b,s,d]
    const int abidx = tid >> 7;       // 0..3
    const int dl = tid & 127;
    const int b = bg + abidx;
    const float4* e4 = (const float4*)(enc + (size_t)b * SS * AA);
#pragma unroll
    for (int rep = 0; rep < 2; ++rep) {
        const int d4 = dl + (rep << 7);   // float4 index 0..255
        float4 acc = make_float4(0.f, 0.f, 0.f, 0.f);
#pragma unroll 8
        for (int s = 0; s < SS; ++s) {
            float w = s_w[abidx][s];
            float4 ev = e4[s * 256 + d4];
            acc.x = fmaf(w, ev.x, acc.x);
            acc.y = fmaf(w, ev.y, acc.y);
            acc.z = fmaf(w, ev.z, acc.z);
            acc.w = fmaf(w, ev.w, acc.w);
        }
        const int d = d4 << 2;
        __nv_bfloat162 h01, l01, h23, l23;
        split2(acc.x, h01.x, l01.x); split2(acc.y, h01.y, l01.y);
        split2(acc.z, h23.x, l23.x); split2(acc.w, h23.y, l23.y);
        size_t base = (size_t)b * 2048 + 1024 + d;
        *(__nv_bfloat162*)&actChi[base]     = h01;
        *(__nv_bfloat162*)&actClo[base]     = l01;
        *(__nv_bfloat162*)&actChi[base + 2] = h23;
        *(__nv_bfloat162*)&actClo[base + 2] = l23;
    }
}

// ---------------------------------------------------------------------------
// GRU gates: r,z,n from gi/gh [B,3H]; h' = (1-z)n + z h (in-place h update)
// ---------------------------------------------------------------------------
__global__ __launch_bounds__(256) void gru_gate_kernel(
    const float* __restrict__ gi, const float* __restrict__ gh,
    float* __restrict__ h,
    __nv_bfloat16* __restrict__ hhi, __nv_bfloat16* __restrict__ hlo)
{
    const int i = blockIdx.x * 256 + threadIdx.x;
    const int b = i >> 10, d = i & 1023;
    const size_t base = (size_t)b * 3072 + d;
    float r = 1.f / (1.f + expf(-(gi[base] + gh[base])));
    float z = 1.f / (1.f + expf(-(gi[base + 1024] + gh[base + 1024])));
    float n = tanhf(gi[base + 2048] + r * gh[base + 2048]);
    float hn = (1.f - z) * n + z * h[i];
    h[i] = hn;
    split2(hn, hhi[i], hlo[i]);
}

// ---------------------------------------------------------------------------
// Setup kernels
// ---------------------------------------------------------------------------
__global__ void split_kernel(const float* __restrict__ src,
                             __nv_bfloat16* __restrict__ hi,
                             __nv_bfloat16* __restrict__ lo, int n)
{
    int i = blockIdx.x * 256 + threadIdx.x;
    if (i < n) split2(src[i], hi[i], lo[i]);
}

__global__ void init_h_kernel(const float* __restrict__ hid,
                              float* __restrict__ h,
                              __nv_bfloat16* __restrict__ hhi,
                              __nv_bfloat16* __restrict__ hlo)
{
    int i = blockIdx.x * 256 + threadIdx.x;
    float v = hid[i];
    h[i] = v;
    split2(v, hhi[i], hlo[i]);
}

__global__ void zero_dec_kernel(__nv_bfloat16* __restrict__ hi,
                                __nv_bfloat16* __restrict__ lo)
{
    int i = blockIdx.x * 256 + threadIdx.x;   // 0 .. 512*1024-1
    int b = i >> 10, d = i & 1023;
    hi[(size_t)b * 2048 + d] = __float2bfloat16(0.f);
    lo[(size_t)b * 2048 + d] = __float2bfloat16(0.f);
}

__global__ void copyf_kernel(const float* __restrict__ s, float* __restrict__ d, int n)
{
    int i = blockIdx.x * 256 + threadIdx.x;
    if (i < n) d[i] = s[i];
}

// ---------------------------------------------------------------------------
extern "C" void kernel_launch(void* const* d_in, const int* in_sizes, int n_in,
                              void* d_out, int out_size)
{
    const float* enc = (const float*)d_in[0];
    const float* hid = (const float*)d_in[1];
    const float* Wa  = (const float*)d_in[3];
    const float* ba  = (const float*)d_in[4];
    const float* Wc  = (const float*)d_in[5];
    const float* bc  = (const float*)d_in[6];
    const float* Wih = (const float*)d_in[7];
    const float* Whh = (const float*)d_in[8];
    const float* bih = (const float*)d_in[9];
    const float* bhh = (const float*)d_in[10];
    const float* Wo  = (const float*)d_in[11];
    const float* bo  = (const float*)d_in[12];

    float* outseq = (float*)d_out;                   // [B, T, O]
    float* outh   = outseq + (size_t)BB * TT * OO;   // [1, B, H]

    // resolve device-global addresses
    __nv_bfloat16 *pWc_hi, *pWc_lo, *pWih_hi, *pWih_lo, *pWhh_hi, *pWhh_lo, *pWo_hi, *pWo_lo;
    __nv_bfloat16 *pactC_hi, *pactC_lo, *pgr_hi, *pgr_lo, *ph_hi, *ph_lo;
    float *ph, *pgi, *pgh, *pzero;
    cudaGetSymbolAddress((void**)&pWc_hi, g_Wc_hi);   cudaGetSymbolAddress((void**)&pWc_lo, g_Wc_lo);
    cudaGetSymbolAddress((void**)&pWih_hi, g_Wih_hi); cudaGetSymbolAddress((void**)&pWih_lo, g_Wih_lo);
    cudaGetSymbolAddress((void**)&pWhh_hi, g_Whh_hi); cudaGetSymbolAddress((void**)&pWhh_lo, g_Whh_lo);
    cudaGetSymbolAddress((void**)&pWo_hi, g_Wo_hi);   cudaGetSymbolAddress((void**)&pWo_lo, g_Wo_lo);
    cudaGetSymbolAddress((void**)&pactC_hi, g_actC_hi); cudaGetSymbolAddress((void**)&pactC_lo, g_actC_lo);
    cudaGetSymbolAddress((void**)&pgr_hi, g_gruin_hi); cudaGetSymbolAddress((void**)&pgr_lo, g_gruin_lo);
    cudaGetSymbolAddress((void**)&ph_hi, g_h_hi);     cudaGetSymbolAddress((void**)&ph_lo, g_h_lo);
    cudaGetSymbolAddress((void**)&ph, g_h);
    cudaGetSymbolAddress((void**)&pgi, g_gi);
    cudaGetSymbolAddress((void**)&pgh, g_gh);
    cudaGetSymbolAddress((void**)&pzero, g_zero);

    // ---- setup: split weights, init h, zero dec region ----
    split_kernel<<<(1024 * 2048 + 255) / 256, 256>>>(Wc, pWc_hi, pWc_lo, 1024 * 2048);
    split_kernel<<<(3072 * 1024 + 255) / 256, 256>>>(Wih, pWih_hi, pWih_lo, 3072 * 1024);
    split_kernel<<<(3072 * 1024 + 255) / 256, 256>>>(Whh, pWhh_hi, pWhh_lo, 3072 * 1024);
    split_kernel<<<(1024 * 1024 + 255) / 256, 256>>>(Wo, pWo_hi, pWo_lo, 1024 * 1024);
    init_h_kernel<<<BB * HH / 256, 256>>>(hid, ph, ph_hi, ph_lo);
    zero_dec_kernel<<<BB * HH / 256, 256>>>(pactC_hi, pactC_lo);

    const dim3 gWc(1024 / 64, 512 / 64, 1);     // 16x8
    const dim3 gGate(3072 / 64, 512 / 64, 2);   // 48x8x2
    const dim3 gWo(1024 / 64, 512 / 64, 1);

    for (int t = 0; t < TT; ++t) {
        const float* dec = (t == 0) ? pzero : (outseq + (size_t)(t - 1) * OO);
        const int ldd = (t == 0) ? 0 : TT * OO;

        // 1. attention (fp32 logits+softmax; writes split attn into actC)
        attn_kernel<<<BB / 4, 512>>>(dec, ldd, ph, enc, Wa, ba, pactC_hi, pactC_lo);

        // 2. gru_in = relu(actC @ Wc^T + bc) -> split bf16
        gemm_split_kernel<<<gWc, 128>>>(
            pactC_hi, pactC_lo, 2048, pWc_hi, pWc_lo, 2048, bc,
            nullptr, 0, pgr_hi, pgr_lo, 1024, 1,
            nullptr, nullptr, nullptr, nullptr, nullptr, nullptr);

        // 3. gi = gruin @ Wih^T + bih ; gh = h @ Whh^T + bhh (batched, z=2)
        gemm_split_kernel<<<gGate, 128>>>(
            pgr_hi, pgr_lo, 1024, pWih_hi, pWih_lo, 1024, bih,
            pgi, 3072, nullptr, nullptr, 0, 0,
            ph_hi, ph_lo, pWhh_hi, pWhh_lo, bhh, pgh);

        // 4. gates -> h (in place) + split
        gru_gate_kernel<<<BB * HH / 256, 256>>>(pgi, pgh, ph, ph_hi, ph_lo);

        // 5. out_tok = h' @ Wo^T + bo -> fp32 outseq + split dec into actC
        gemm_split_kernel<<<gWo, 128>>>(
            ph_hi, ph_lo, 1024, pWo_hi, pWo_lo, 1024, bo,
            outseq + (size_t)t * OO, TT * OO, pactC_hi, pactC_lo, 2048, 2,
            nullptr, nullptr, nullptr, nullptr, nullptr, nullptr);
    }

    // final hidden state
    if (out_size >= BB * TT * OO + BB * HH) {
        copyf_kernel<<<BB * HH / 256, 256>>>(ph, outh, BB * HH);
    }
}

// round 5
// speedup vs baseline: 3.2209x; 1.4907x over previous
#include <cuda_runtime.h>
#include <cuda_bf16.h>
#include <cstdint>

#define BB 512
#define HH 1024
#define OO 1024
#define SS 64
#define TT 128

// ---------------------------------------------------------------------------
// Device-global scratch (allocation-free)
// ---------------------------------------------------------------------------
__device__ __align__(256) __nv_bfloat16 g_Wih_hi[3072 * 1024], g_Wih_lo[3072 * 1024];
__device__ __align__(256) __nv_bfloat16 g_Whh_hi[3072 * 1024], g_Whh_lo[3072 * 1024];
__device__ __align__(256) __nv_bfloat16 g_Wo_hi[1024 * 1024], g_Wo_lo[1024 * 1024];
__device__ __align__(256) __nv_bfloat16 g_WoT_hi[1024 * 1024], g_WoT_lo[1024 * 1024];
__device__ __align__(256) __nv_bfloat16 g_Wc1_hi[1024 * 1024], g_Wc1_lo[1024 * 1024];
__device__ __align__(256) __nv_bfloat16 g_WcK_hi[1024 * 2048], g_WcK_lo[1024 * 2048];
__device__ __align__(256) float g_WaF[64 * 1024];
__device__ __align__(256) float g_baF[64];
__device__ __align__(256) float g_bcF[1024];
__device__ __align__(256) __nv_bfloat16 g_actC_hi[512 * 2048], g_actC_lo[512 * 2048]; // [h | attn]
__device__ __align__(256) __nv_bfloat16 g_gr_hi[512 * 1024], g_gr_lo[512 * 1024];
__device__ __align__(256) __nv_bfloat16 g_Hall_hi[(size_t)512 * 128 * 1024];
__device__ __align__(256) __nv_bfloat16 g_Hall_lo[(size_t)512 * 128 * 1024];
__device__ __align__(256) float g_h[512 * 1024];
__device__ __align__(256) float g_gi[512 * 3072], g_gh[512 * 3072];
__device__ __align__(256) float g_zero[4096];

// ---------------------------------------------------------------------------
// Helpers
// ---------------------------------------------------------------------------
__device__ __forceinline__ void split2(float v, __nv_bfloat16& hi, __nv_bfloat16& lo) {
    hi = __float2bfloat16(v);
    lo = __float2bfloat16(v - __bfloat162float(hi));
}

__device__ __forceinline__ uint32_t smem_u32(const void* p) {
    uint32_t a;
    asm("{ .reg .u64 t; cvta.to.shared.u64 t, %1; cvt.u32.u64 %0, t; }" : "=r"(a) : "l"(p));
    return a;
}

__device__ __forceinline__ void ldsm_x4(uint32_t* r, uint32_t addr) {
    asm volatile("ldmatrix.sync.aligned.m8n8.x4.shared.b16 {%0,%1,%2,%3}, [%4];\n"
                 : "=r"(r[0]), "=r"(r[1]), "=r"(r[2]), "=r"(r[3]) : "r"(addr));
}

__device__ __forceinline__ void mma_bf16(float* c, const uint32_t* a, const uint32_t* b) {
    asm volatile(
        "mma.sync.aligned.m16n8k16.row.col.f32.bf16.bf16.f32 "
        "{%0,%1,%2,%3}, {%4,%5,%6,%7}, {%8,%9}, {%0,%1,%2,%3};\n"
        : "+f"(c[0]), "+f"(c[1]), "+f"(c[2]), "+f"(c[3])
        : "r"(a[0]), "r"(a[1]), "r"(a[2]), "r"(a[3]), "r"(b[0]), "r"(b[1]));
}

__device__ __forceinline__ void cp16a(uint32_t dst, const void* src) {
    asm volatile("cp.async.cg.shared.global [%0], [%1], 16;\n" :: "r"(dst), "l"(src));
}
#define CP_COMMIT() asm volatile("cp.async.commit_group;\n" ::: "memory")
#define CP_WAIT1()  asm volatile("cp.async.wait_group 1;\n" ::: "memory")

// ---------------------------------------------------------------------------
// Fused 3-pass split-bf16 GEMM: C[M,N] = A@W^T + bias via
// Ahi@Whi + Ahi@Wlo + Alo@Whi in ONE K-loop, fp32 accum.
// Tile 64(M) x 128(N), BK=32, 256 threads (2x4 warps, warp tile 32x32).
// Row stride 56 elem (112B): 16B-aligned cp.async, conflict-free ldmatrix.
// mode 0: fp32 out; 1: relu -> split bf16; 2: split bf16 (no relu).
// blockIdx.z picks one of two problem descriptors.
// Stage layout (bytes): Ahi 0, Alo 7168, Whi 14336, Wlo 28672; stage=43008.
// ---------------------------------------------------------------------------
struct GProb {
    const __nv_bfloat16 *Ahi, *Alo; int lda;
    const __nv_bfloat16 *Whi, *Wlo; int ldw;
    int K;
    const float* bias;
    float* Cf; int ldc;
    __nv_bfloat16 *Chi, *Clo; int ldch;
    int mode;
};
struct GP2 { GProb p[2]; };

__global__ __launch_bounds__(256, 2) void gemm_fused_kernel(GP2 P)
{
    const GProb p = P.p[blockIdx.z];
    extern __shared__ __nv_bfloat16 smg[];
    const uint32_t smbase = smem_u32(smg);

    const int tid = threadIdx.x, warp = tid >> 5, lane = tid & 31;
    const int m0 = blockIdx.y * 64, n0 = blockIdx.x * 128;
    const int S = p.K >> 5;
    const int wm = warp >> 2, wn = warp & 3;
    const int lr = tid >> 2;             // 0..63 loader row
    const int lk = (tid & 3) << 3;       // 0,8,16,24 loader k offset

    float acc[2][4][4];
#pragma unroll
    for (int mi = 0; mi < 2; ++mi)
#pragma unroll
        for (int nf = 0; nf < 4; ++nf)
#pragma unroll
            for (int q = 0; q < 4; ++q) acc[mi][nf][q] = 0.f;

    auto load_stage = [&](int s) {
        const int k0 = s << 5;
        const uint32_t sb = smbase + (uint32_t)(s & 1) * 43008u;
        const uint32_t ao = (uint32_t)(lr * 56 + lk) * 2;
        cp16a(sb + ao, p.Ahi + (size_t)(m0 + lr) * p.lda + k0 + lk);
        cp16a(sb + 7168 + ao, p.Alo + (size_t)(m0 + lr) * p.lda + k0 + lk);
        const __nv_bfloat16* w1 = p.Whi + (size_t)(n0 + lr) * p.ldw + k0 + lk;
        const __nv_bfloat16* w2 = p.Wlo + (size_t)(n0 + lr) * p.ldw + k0 + lk;
        const uint32_t wo2 = (uint32_t)((lr + 64) * 56 + lk) * 2;
        cp16a(sb + 14336 + ao, w1);
        cp16a(sb + 14336 + wo2, w1 + (size_t)64 * p.ldw);
        cp16a(sb + 28672 + ao, w2);
        cp16a(sb + 28672 + wo2, w2 + (size_t)64 * p.ldw);
    };

    load_stage(0); CP_COMMIT();
    load_stage(1); CP_COMMIT();

    for (int s = 0; s < S; ++s) {
        CP_WAIT1();
        __syncthreads();
        const uint32_t sb = smbase + (uint32_t)(s & 1) * 43008u;
#pragma unroll
        for (int kk = 0; kk < 2; ++kk) {
            const int arow = wm * 32 + (lane & 15);
            const int acol = kk * 16 + ((lane >> 4) << 3);
            uint32_t ahi[2][4], alo[2][4];
#pragma unroll
            for (int mi = 0; mi < 2; ++mi) {
                const uint32_t off = (uint32_t)((arow + mi * 16) * 56 + acol) * 2;
                ldsm_x4(ahi[mi], sb + off);
                ldsm_x4(alo[mi], sb + 7168 + off);
            }
            const int g = lane >> 3;
            const int brow = wn * 32 + ((g >> 1) << 3) + (lane & 7);
            const int bcol = kk * 16 + ((g & 1) << 3);
            uint32_t bhi[4][2], blo[4][2];
#pragma unroll
            for (int nh = 0; nh < 2; ++nh) {
                uint32_t r[4];
                const uint32_t off = (uint32_t)((brow + nh * 16) * 56 + bcol) * 2;
                ldsm_x4(r, sb + 14336 + off);
                bhi[nh * 2 + 0][0] = r[0]; bhi[nh * 2 + 0][1] = r[1];
                bhi[nh * 2 + 1][0] = r[2]; bhi[nh * 2 + 1][1] = r[3];
                ldsm_x4(r, sb + 28672 + off);
                blo[nh * 2 + 0][0] = r[0]; blo[nh * 2 + 0][1] = r[1];
                blo[nh * 2 + 1][0] = r[2]; blo[nh * 2 + 1][1] = r[3];
            }
#pragma unroll
            for (int mi = 0; mi < 2; ++mi)
#pragma unroll
                for (int nf = 0; nf < 4; ++nf)
                    mma_bf16(acc[mi][nf], ahi[mi], bhi[nf]);
#pragma unroll
            for (int mi = 0; mi < 2; ++mi)
#pragma unroll
                for (int nf = 0; nf < 4; ++nf)
                    mma_bf16(acc[mi][nf], ahi[mi], blo[nf]);
#pragma unroll
            for (int mi = 0; mi < 2; ++mi)
#pragma unroll
                for (int nf = 0; nf < 4; ++nf)
                    mma_bf16(acc[mi][nf], alo[mi], bhi[nf]);
        }
        __syncthreads();
        if (s + 2 < S) load_stage(s + 2);
        CP_COMMIT();
    }

    // Epilogue
    const int row0 = m0 + wm * 32 + (lane >> 2);
    const int col0 = n0 + wn * 32 + ((lane & 3) << 1);
#pragma unroll
    for (int mi = 0; mi < 2; ++mi) {
#pragma unroll
        for (int nf = 0; nf < 4; ++nf) {
            const int col = col0 + nf * 8;
            const float b0 = p.bias[col], b1 = p.bias[col + 1];
#pragma unroll
            for (int half = 0; half < 2; ++half) {
                const int row = row0 + mi * 16 + half * 8;
                float v0 = acc[mi][nf][half * 2 + 0] + b0;
                float v1 = acc[mi][nf][half * 2 + 1] + b1;
                if (p.mode == 0) {
                    *(float2*)&p.Cf[(size_t)row * p.ldc + col] = make_float2(v0, v1);
                } else {
                    if (p.mode == 1) { v0 = fmaxf(v0, 0.f); v1 = fmaxf(v1, 0.f); }
                    __nv_bfloat162 hv, lv;
                    split2(v0, hv.x, lv.x); split2(v1, hv.y, lv.y);
                    *(__nv_bfloat162*)&p.Chi[(size_t)row * p.ldch + col] = hv;
                    *(__nv_bfloat162*)&p.Clo[(size_t)row * p.ldch + col] = lv;
                }
            }
        }
    }
}

// ---------------------------------------------------------------------------
// Fused attention: logits = h @ W^T + bias (K=1024), softmax(64), apply.
// 4 batch rows / block, 512 threads. Writes attn split into actC[:,1024:2048).
// ---------------------------------------------------------------------------
__global__ __launch_bounds__(512) void attn_kernel(
    const float* __restrict__ h,
    const float* __restrict__ enc,
    const float* __restrict__ W, int wld, const float* __restrict__ bias,
    __nv_bfloat16* __restrict__ actChi, __nv_bfloat16* __restrict__ actClo)
{
    __shared__ float s_temp[4][1024];
    __shared__ float s_logit[4][64];
    __shared__ float s_w[4][64];

    const int tid = threadIdx.x;
    const int bg = blockIdx.x << 2;

    for (int i = tid; i < 4 * 1024; i += 512) {
        const int bi = i >> 10, j = i & 1023;
        s_temp[bi][j] = h[(size_t)(bg + bi) * 1024 + j];
    }
    __syncthreads();

    const int warp = tid >> 5, lane = tid & 31;
    const int bi = warp & 3, og = warp >> 2;
    const float4* t4 = (const float4*)s_temp[bi];

#pragma unroll 1
    for (int j = 0; j < 16; ++j) {
        const int o = og * 16 + j;
        const float4* w4 = (const float4*)(W + (size_t)o * wld);
        float acc = 0.f;
#pragma unroll
        for (int i = 0; i < 8; ++i) {
            float4 wv = w4[lane + (i << 5)];
            float4 tv = t4[lane + (i << 5)];
            acc = fmaf(wv.x, tv.x, fmaf(wv.y, tv.y,
                  fmaf(wv.z, tv.z, fmaf(wv.w, tv.w, acc))));
        }
#pragma unroll
        for (int off = 16; off > 0; off >>= 1)
            acc += __shfl_xor_sync(0xffffffffu, acc, off);
        if (lane == 0) s_logit[bi][o] = acc + bias[o];
    }
    __syncthreads();

    if (warp < 4) {
        float v0 = s_logit[warp][lane], v1 = s_logit[warp][lane + 32];
        float m = fmaxf(v0, v1);
#pragma unroll
        for (int off = 16; off > 0; off >>= 1)
            m = fmaxf(m, __shfl_xor_sync(0xffffffffu, m, off));
        float e0 = expf(v0 - m), e1 = expf(v1 - m);
        float s = e0 + e1;
#pragma unroll
        for (int off = 16; off > 0; off >>= 1)
            s += __shfl_xor_sync(0xffffffffu, s, off);
        float inv = 1.f / s;
        s_w[warp][lane] = e0 * inv;
        s_w[warp][lane + 32] = e1 * inv;
    }
    __syncthreads();

    const int abidx = tid >> 7;
    const int dl = tid & 127;
    const int b = bg + abidx;
    const float4* e4 = (const float4*)(enc + (size_t)b * SS * 1024);
#pragma unroll
    for (int rep = 0; rep < 2; ++rep) {
        const int d4 = dl + (rep << 7);
        float4 acc = make_float4(0.f, 0.f, 0.f, 0.f);
#pragma unroll 8
        for (int s = 0; s < SS; ++s) {
            float w = s_w[abidx][s];
            float4 ev = e4[s * 256 + d4];
            acc.x = fmaf(w, ev.x, acc.x);
            acc.y = fmaf(w, ev.y, acc.y);
            acc.z = fmaf(w, ev.z, acc.z);
            acc.w = fmaf(w, ev.w, acc.w);
        }
        const int d = d4 << 2;
        __nv_bfloat162 h01, l01, h23, l23;
        split2(acc.x, h01.x, l01.x); split2(acc.y, h01.y, l01.y);
        split2(acc.z, h23.x, l23.x); split2(acc.w, h23.y, l23.y);
        size_t base = (size_t)b * 2048 + 1024 + d;
        *(__nv_bfloat162*)&actChi[base]     = h01;
        *(__nv_bfloat162*)&actClo[base]     = l01;
        *(__nv_bfloat162*)&actChi[base + 2] = h23;
        *(__nv_bfloat162*)&actClo[base + 2] = l23;
    }
}

// ---------------------------------------------------------------------------
// GRU gates; writes h fp32, h split into actC[:,0:1024), and Hall[b][t].
// ---------------------------------------------------------------------------
__global__ __launch_bounds__(256) void gru_gate_kernel(
    const float* __restrict__ gi, const float* __restrict__ gh,
    float* __restrict__ h,
    __nv_bfloat16* __restrict__ actChi, __nv_bfloat16* __restrict__ actClo,
    __nv_bfloat16* __restrict__ Hhi, __nv_bfloat16* __restrict__ Hlo, int t)
{
    const int i = blockIdx.x * 256 + threadIdx.x;
    const int b = i >> 10, d = i & 1023;
    const size_t base = (size_t)b * 3072 + d;
    float r = 1.f / (1.f + expf(-(gi[base] + gh[base])));
    float z = 1.f / (1.f + expf(-(gi[base + 1024] + gh[base + 1024])));
    float n = tanhf(gi[base + 2048] + r * gh[base + 2048]);
    float hn = (1.f - z) * n + z * h[i];
    h[i] = hn;
    __nv_bfloat16 hi, lo;
    split2(hn, hi, lo);
    actChi[(size_t)b * 2048 + d] = hi;
    actClo[(size_t)b * 2048 + d] = lo;
    const size_t hidx = ((size_t)b * 128 + t) * 1024 + d;
    Hhi[hidx] = hi;
    Hlo[hidx] = lo;
}

// ---------------------------------------------------------------------------
// Setup kernels
// ---------------------------------------------------------------------------
__global__ void split_mat_kernel(const float* __restrict__ src, int sld, int cols,
                                 __nv_bfloat16* __restrict__ dhi,
                                 __nv_bfloat16* __restrict__ dlo, int dld, int total)
{
    int i = blockIdx.x * 256 + threadIdx.x;
    if (i >= total) return;
    int r = i / cols, c = i - r * cols;
    split2(src[(size_t)r * sld + c], dhi[(size_t)r * dld + c], dlo[(size_t)r * dld + c]);
}

// WoT[j][i] = Wo[i][j], split. grid (32,32), block (32,8).
__global__ void transpose_split_kernel(const float* __restrict__ src,
                                       __nv_bfloat16* __restrict__ dhi,
                                       __nv_bfloat16* __restrict__ dlo)
{
    __shared__ float tile[32][33];
    const int bx = blockIdx.x * 32, by = blockIdx.y * 32;
#pragma unroll
    for (int r = 0; r < 4; ++r)
        tile[threadIdx.y + 8 * r][threadIdx.x] =
            src[(size_t)(by + threadIdx.y + 8 * r) * 1024 + bx + threadIdx.x];
    __syncthreads();
#pragma unroll
    for (int r = 0; r < 4; ++r) {
        float v = tile[threadIdx.x][threadIdx.y + 8 * r];
        size_t o = (size_t)(bx + threadIdx.y + 8 * r) * 1024 + by + threadIdx.x;
        split2(v, dhi[o], dlo[o]);
    }
}

// WaF[o][j] = Wa[o][1024+j] + sum_k Wa[o][k]*Wo[k][j]; baF[o] = ba[o] + Wa1[o]·bo
__global__ __launch_bounds__(256) void fold_wa_kernel(
    const float* __restrict__ Wa, const float* __restrict__ Wo,
    const float* __restrict__ ba, const float* __restrict__ bo,
    float* __restrict__ WaF, float* __restrict__ baF)
{
    __shared__ float wa1[1024];
    const int o = blockIdx.x, tid = threadIdx.x;
    for (int i = tid; i < 1024; i += 256) wa1[i] = Wa[(size_t)o * 2048 + i];
    __syncthreads();
    for (int j = tid; j < 1024; j += 256) {
        float acc = Wa[(size_t)o * 2048 + 1024 + j];
        for (int k = 0; k < 1024; ++k)
            acc = fmaf(wa1[k], Wo[(size_t)k * 1024 + j], acc);
        WaF[(size_t)o * 1024 + j] = acc;
    }
    if (tid < 32) {
        float s = 0.f;
        for (int k = tid; k < 1024; k += 32) s += wa1[k] * bo[k];
#pragma unroll
        for (int off = 16; off > 0; off >>= 1)
            s += __shfl_xor_sync(0xffffffffu, s, off);
        if (tid == 0) baF[o] = ba[o] + s;
    }
}

// bcF[n] = bc[n] + Wc1[n]·bo  (Wc row stride 2048)
__global__ __launch_bounds__(256) void fold_bc_kernel(
    const float* __restrict__ Wc, const float* __restrict__ bo,
    const float* __restrict__ bc, float* __restrict__ bcF)
{
    const int n = blockIdx.x * 8 + (threadIdx.x >> 5);
    const int lane = threadIdx.x & 31;
    float s = 0.f;
    for (int k = lane; k < 1024; k += 32) s += Wc[(size_t)n * 2048 + k] * bo[k];
#pragma unroll
    for (int off = 16; off > 0; off >>= 1)
        s += __shfl_xor_sync(0xffffffffu, s, off);
    if (lane == 0) bcF[n] = bc[n] + s;
}

__global__ void init_h_kernel(const float* __restrict__ hid, float* __restrict__ h,
                              __nv_bfloat16* __restrict__ actChi,
                              __nv_bfloat16* __restrict__ actClo)
{
    int i = blockIdx.x * 256 + threadIdx.x;
    int b = i >> 10, d = i & 1023;
    float v = hid[i];
    h[i] = v;
    split2(v, actChi[(size_t)b * 2048 + d], actClo[(size_t)b * 2048 + d]);
}

__global__ void copyf_kernel(const float* __restrict__ s, float* __restrict__ d, int n)
{
    int i = blockIdx.x * 256 + threadIdx.x;
    if (i < n) d[i] = s[i];
}

// ---------------------------------------------------------------------------
extern "C" void kernel_launch(void* const* d_in, const int* in_sizes, int n_in,
                              void* d_out, int out_size)
{
    const float* enc = (const float*)d_in[0];
    const float* hid = (const float*)d_in[1];
    const float* Wa  = (const float*)d_in[3];
    const float* ba  = (const float*)d_in[4];
    const float* Wc  = (const float*)d_in[5];
    const float* bc  = (const float*)d_in[6];
    const float* Wih = (const float*)d_in[7];
    const float* Whh = (const float*)d_in[8];
    const float* bih = (const float*)d_in[9];
    const float* bhh = (const float*)d_in[10];
    const float* Wo  = (const float*)d_in[11];
    const float* bo  = (const float*)d_in[12];

    float* outseq = (float*)d_out;
    float* outh   = outseq + (size_t)BB * TT * OO;

    __nv_bfloat16 *pWih_hi, *pWih_lo, *pWhh_hi, *pWhh_lo, *pWo_hi, *pWo_lo;
    __nv_bfloat16 *pWoT_hi, *pWoT_lo, *pWc1_hi, *pWc1_lo, *pWcK_hi, *pWcK_lo;
    __nv_bfloat16 *pactC_hi, *pactC_lo, *pgr_hi, *pgr_lo, *pH_hi, *pH_lo;
    float *ph, *pgi, *pgh, *pzero, *pWaF, *pbaF, *pbcF;
    cudaGetSymbolAddress((void**)&pWih_hi, g_Wih_hi); cudaGetSymbolAddress((void**)&pWih_lo, g_Wih_lo);
    cudaGetSymbolAddress((void**)&pWhh_hi, g_Whh_hi); cudaGetSymbolAddress((void**)&pWhh_lo, g_Whh_lo);
    cudaGetSymbolAddress((void**)&pWo_hi, g_Wo_hi);   cudaGetSymbolAddress((void**)&pWo_lo, g_Wo_lo);
    cudaGetSymbolAddress((void**)&pWoT_hi, g_WoT_hi); cudaGetSymbolAddress((void**)&pWoT_lo, g_WoT_lo);
    cudaGetSymbolAddress((void**)&pWc1_hi, g_Wc1_hi); cudaGetSymbolAddress((void**)&pWc1_lo, g_Wc1_lo);
    cudaGetSymbolAddress((void**)&pWcK_hi, g_WcK_hi); cudaGetSymbolAddress((void**)&pWcK_lo, g_WcK_lo);
    cudaGetSymbolAddress((void**)&pactC_hi, g_actC_hi); cudaGetSymbolAddress((void**)&pactC_lo, g_actC_lo);
    cudaGetSymbolAddress((void**)&pgr_hi, g_gr_hi);   cudaGetSymbolAddress((void**)&pgr_lo, g_gr_lo);
    cudaGetSymbolAddress((void**)&pH_hi, g_Hall_hi);  cudaGetSymbolAddress((void**)&pH_lo, g_Hall_lo);
    cudaGetSymbolAddress((void**)&ph, g_h);
    cudaGetSymbolAddress((void**)&pgi, g_gi);
    cudaGetSymbolAddress((void**)&pgh, g_gh);
    cudaGetSymbolAddress((void**)&pzero, g_zero);
    cudaGetSymbolAddress((void**)&pWaF, g_WaF);
    cudaGetSymbolAddress((void**)&pbaF, g_baF);
    cudaGetSymbolAddress((void**)&pbcF, g_bcF);

    const int GEMM_SMEM = 86016;
    cudaFuncSetAttribute(gemm_fused_kernel, cudaFuncAttributeMaxDynamicSharedMemorySize, GEMM_SMEM);

    // ---- setup ----
    split_mat_kernel<<<(3072 * 1024 + 255) / 256, 256>>>(Wih, 1024, 1024, pWih_hi, pWih_lo, 1024, 3072 * 1024);
    split_mat_kernel<<<(3072 * 1024 + 255) / 256, 256>>>(Whh, 1024, 1024, pWhh_hi, pWhh_lo, 1024, 3072 * 1024);
    split_mat_kernel<<<(1024 * 1024 + 255) / 256, 256>>>(Wo, 1024, 1024, pWo_hi, pWo_lo, 1024, 1024 * 1024);
    split_mat_kernel<<<(1024 * 1024 + 255) / 256, 256>>>(Wc + 1024, 2048, 1024, pWcK_hi + 1024, pWcK_lo + 1024, 2048, 1024 * 1024);
    split_mat_kernel<<<(1024 * 1024 + 255) / 256, 256>>>(Wc, 2048, 1024, pWc1_hi, pWc1_lo, 1024, 1024 * 1024);
    transpose_split_kernel<<<dim3(32, 32), dim3(32, 8)>>>(Wo, pWoT_hi, pWoT_lo);
    fold_wa_kernel<<<64, 256>>>(Wa, Wo, ba, bo, pWaF, pbaF);
    fold_bc_kernel<<<128, 256>>>(Wc, bo, bc, pbcF);
    init_h_kernel<<<BB * HH / 256, 256>>>(hid, ph, pactC_hi, pactC_lo);

    // WcF = Wc1 @ Wo -> split into WcK cols [0,1024)
    {
        GP2 P{};
        P.p[0] = { pWc1_hi, pWc1_lo, 1024, pWoT_hi, pWoT_lo, 1024, 1024,
                   pzero, nullptr, 0, pWcK_hi, pWcK_lo, 2048, 2 };
        gemm_fused_kernel<<<dim3(8, 16, 1), 256, GEMM_SMEM>>>(P);
    }

    for (int t = 0; t < TT; ++t) {
        // 1. attention
        if (t == 0)
            attn_kernel<<<BB / 4, 512>>>(ph, enc, Wa + 1024, 2048, ba, pactC_hi, pactC_lo);
        else
            attn_kernel<<<BB / 4, 512>>>(ph, enc, pWaF, 1024, pbaF, pactC_hi, pactC_lo);

        // 2. gru_in = relu([h|attn] @ [WcF|Wc2]^T + bcF)   (t=0: attn@Wc2^T + bc)
        {
            GP2 P{};
            if (t == 0)
                P.p[0] = { pactC_hi + 1024, pactC_lo + 1024, 2048, pWcK_hi + 1024, pWcK_lo + 1024, 2048,
                           1024, bc, nullptr, 0, pgr_hi, pgr_lo, 1024, 1 };
            else
                P.p[0] = { pactC_hi, pactC_lo, 2048, pWcK_hi, pWcK_lo, 2048,
                           2048, pbcF, nullptr, 0, pgr_hi, pgr_lo, 1024, 1 };
            gemm_fused_kernel<<<dim3(8, 8, 1), 256, GEMM_SMEM>>>(P);
        }

        // 3. gi = gruin @ Wih^T + bih ; gh = h @ Whh^T + bhh
        {
            GP2 P{};
            P.p[0] = { pgr_hi, pgr_lo, 1024, pWih_hi, pWih_lo, 1024, 1024,
                       bih, pgi, 3072, nullptr, nullptr, 0, 0 };
            P.p[1] = { pactC_hi, pactC_lo, 2048, pWhh_hi, pWhh_lo, 1024, 1024,
                       bhh, pgh, 3072, nullptr, nullptr, 0, 0 };
            gemm_fused_kernel<<<dim3(24, 8, 2), 256, GEMM_SMEM>>>(P);
        }

        // 4. gates -> h, actC h-cols, Hall[b][t]
        gru_gate_kernel<<<BB * HH / 256, 256>>>(pgi, pgh, ph, pactC_hi, pactC_lo, pH_hi, pH_lo, t);
    }

    // 5. outseq = Hall @ Wo^T + bo  (M = 512*128, row = b*128+t -> contiguous)
    {
        GP2 P{};
        P.p[0] = { pH_hi, pH_lo, 1024, pWo_hi, pWo_lo, 1024, 1024,
                   bo, outseq, 1024, nullptr, nullptr, 0, 0 };
        gemm_fused_kernel<<<dim3(8, 1024, 1), 256, GEMM_SMEM>>>(P);
    }

    if (out_size >= BB * TT * OO + BB * HH) {
        copyf_kernel<<<BB * HH / 256, 256>>>(ph, outh, BB * HH);
    }
}